// round 2
// baseline (speedup 1.0000x reference)
#include <cuda_runtime.h>
#include <cstddef>

// Problem constants (from reference setup_inputs)
#define B_      64
#define S_      2048
#define D_      768
#define D4_     192          // D_/4 float4s per row
#define POOL_   32
#define L_      8
#define TOPK_   4
#define NTILE_  16           // S_ / SBLK_
#define SBLK_   128
#define PREFIX_ 41           // L_ + TOPK_*L_ + 1
#define OUTROWS_ 2089        // PREFIX_ + S_

// Scratch: per-(batch, tile) partial sums of x over the seq dimension.
__device__ float g_partial[B_ * NTILE_ * D_];

// ---------------------------------------------------------------------------
// Kernel A: stream x -> out[:, 41:, :] while accumulating per-(b,d) partial
// sums per s-tile. Reads x exactly once (403 MB), writes 403 MB.
// grid = (NTILE_, B_), block = 768 threads. Thread (r,c): r = row-phase 0..3,
// c = float4 column 0..191. Coalesced float4 loads/stores.
// ---------------------------------------------------------------------------
__global__ __launch_bounds__(768, 2)
void copy_reduce_kernel(const float4* __restrict__ x4,
                        float4* __restrict__ out4,
                        float4* __restrict__ part4)
{
    const int tile = blockIdx.x;
    const int b    = blockIdx.y;
    const int tid  = threadIdx.x;
    const int r    = tid / D4_;   // 0..3
    const int c    = tid % D4_;   // 0..191

    const int s0 = tile * SBLK_;
    const float4* src = x4  + ((size_t)b * S_ + s0) * D4_ + c;
    float4*       dst = out4 + ((size_t)b * OUTROWS_ + PREFIX_ + s0) * D4_ + c;

    float4 acc = make_float4(0.f, 0.f, 0.f, 0.f);
    #pragma unroll 4
    for (int s = r; s < SBLK_; s += 4) {
        float4 v = src[(size_t)s * D4_];
        dst[(size_t)s * D4_] = v;
        acc.x += v.x; acc.y += v.y; acc.z += v.z; acc.w += v.w;
    }

    __shared__ float4 red[768];
    red[tid] = acc;
    __syncthreads();

    if (r == 0) {
        float4 a0 = red[c];
        float4 a1 = red[D4_ + c];
        float4 a2 = red[2 * D4_ + c];
        float4 a3 = red[3 * D4_ + c];
        float4 s;
        s.x = (a0.x + a1.x) + (a2.x + a3.x);
        s.y = (a0.y + a1.y) + (a2.y + a3.y);
        s.z = (a0.z + a1.z) + (a2.z + a3.z);
        s.w = (a0.w + a1.w) + (a2.w + a3.w);
        part4[((size_t)b * NTILE_ + tile) * D4_ + c] = s;
    }
}

// ---------------------------------------------------------------------------
// Kernel B: per batch b (64 blocks, 256 threads):
//   1. reduce the 16 tile-partials -> query sum (smem)
//   2. sim[p] = dot(q, k_p) * rsqrt(|k_p|^2 + eps)   (ranking-equivalent to ref)
//   3. stable top-4 (descending, lower index wins ties == lax.top_k)
//   4. write the 41 prefix rows: g_prompts[task_id] | selected e_prompts | cls
// ---------------------------------------------------------------------------
__global__ __launch_bounds__(256)
void select_write_kernel(const float* __restrict__ g_prompts,
                         const float* __restrict__ e_prompts,
                         const float* __restrict__ e_keys,
                         const float* __restrict__ cls_token,
                         const int*   __restrict__ task_id,
                         const float* __restrict__ part,
                         float*       __restrict__ out)
{
    const int b   = blockIdx.x;
    const int tid = threadIdx.x;

    __shared__ float q[D_];
    __shared__ float sim[POOL_];
    __shared__ int   sel[TOPK_];

    // 1. reduce tile partials
    for (int d = tid; d < D_; d += 256) {
        const float* p = part + (size_t)b * NTILE_ * D_ + d;
        float s = 0.f;
        #pragma unroll
        for (int t = 0; t < NTILE_; t++) s += p[(size_t)t * D_];
        q[d] = s;
    }
    __syncthreads();

    // 2. similarity: warp w handles pools w, w+8, w+16, w+24
    const int warp = tid >> 5, lane = tid & 31;
    for (int p = warp; p < POOL_; p += 8) {
        const float* k = e_keys + (size_t)p * D_;
        float dot = 0.f, kk = 0.f;
        for (int d = lane; d < D_; d += 32) {
            float kv = k[d];
            dot += q[d] * kv;
            kk  += kv * kv;
        }
        #pragma unroll
        for (int off = 16; off; off >>= 1) {
            dot += __shfl_xor_sync(0xffffffffu, dot, off);
            kk  += __shfl_xor_sync(0xffffffffu, kk,  off);
        }
        if (lane == 0) sim[p] = dot * rsqrtf(kk + 1e-12f);
    }
    __syncthreads();

    // 3. top-4 selection (strict >, first occurrence wins: matches lax.top_k)
    if (tid == 0) {
        unsigned used = 0;
        #pragma unroll
        for (int kI = 0; kI < TOPK_; kI++) {
            int best = -1; float bv = -3.4e38f;
            for (int p = 0; p < POOL_; p++) {
                if (used & (1u << p)) continue;
                if (sim[p] > bv) { bv = sim[p]; best = p; }
            }
            used |= (1u << best);
            sel[kI] = best;
        }
    }
    __syncthreads();

    // 4. write prefix rows
    const int t_id = task_id[0];
    const float4* g4 = (const float4*)g_prompts + (size_t)t_id * L_ * D4_;
    const float4* e4 = (const float4*)e_prompts;
    const float4* c4 = (const float4*)cls_token;
    float4* o4 = (float4*)out + (size_t)b * OUTROWS_ * D4_;

    for (int i = tid; i < PREFIX_ * D4_; i += 256) {
        const int row = i / D4_;
        const int c   = i % D4_;
        float4 v;
        if (row < L_) {
            v = g4[row * D4_ + c];
        } else if (row < L_ + TOPK_ * L_) {
            const int e  = row - L_;
            const int j  = e >> 3;        // which selected block
            const int rr = e & 7;         // row within block
            v = e4[((size_t)sel[j] * L_ + rr) * D4_ + c];
        } else {
            v = c4[c];
        }
        o4[i] = v;
    }
}

// ---------------------------------------------------------------------------
// Launch: A then B on the same stream (graph nodes serialize). No allocs,
// no syncs, deterministic.
// ---------------------------------------------------------------------------
extern "C" void kernel_launch(void* const* d_in, const int* in_sizes, int n_in,
                              void* d_out, int out_size)
{
    const float* x         = (const float*)d_in[0];
    const float* g_prompts = (const float*)d_in[1];
    const float* e_prompts = (const float*)d_in[2];
    const float* e_keys    = (const float*)d_in[3];
    const float* cls_token = (const float*)d_in[4];
    const int*   task_id   = (const int*)  d_in[5];
    float* out = (float*)d_out;

    float* part;
    cudaGetSymbolAddress((void**)&part, g_partial);

    dim3 gridA(NTILE_, B_);
    copy_reduce_kernel<<<gridA, 768>>>((const float4*)x,
                                       (float4*)out,
                                       (float4*)part);

    select_write_kernel<<<B_, 256>>>(g_prompts, e_prompts, e_keys,
                                     cls_token, task_id, part, out);
}